// round 1
// baseline (speedup 1.0000x reference)
#include <cuda_runtime.h>
#include <math.h>

#define BATCH 64
#define LSEQ 512
#define FDIM 41
#define HDIM 128
#define NLAYER 2
#define DSTATE 16
#define DCONV 4
#define DINNER 256
#define DTRANK 8
#define NE 3
#define NT 100
#define NFC 160
#define BL (BATCH*LSEQ)
#define XDBW (DTRANK + 2*DSTATE)   /* 40 */
#define ATTN_SCALE 0.08838834764831845f  /* 1/sqrt(128) */

// ---------------- static device scratch (no allocation allowed) ----------------
__device__ float g_h [BL*HDIM];     // residual stream
__device__ float g_hn[BL*HDIM];     // layernorm output / final hidden
__device__ float g_u [BL*DINNER];   // pre-conv u
__device__ float g_uc[BL*DINNER];   // post-conv silu(u)
__device__ float g_z [BL*DINNER];   // silu(z)
__device__ float g_xdb[BL*XDBW];
__device__ float g_dt[BL*DINNER];
__device__ float g_y [BL*DINNER];
__device__ float g_last[BATCH*HDIM];
__device__ float g_qk [BATCH*HDIM];
__device__ float g_qbias[BATCH];
__device__ float g_sr [BATCH*HDIM];

__device__ __forceinline__ float siluf(float x){ return x / (1.f + __expf(-x)); }

// ---------------- input projection: h = x @ ip_W^T + ip_b ----------------
__global__ void k_inproj(const float* __restrict__ x, const float* __restrict__ W,
                         const float* __restrict__ bias){
    int tok = blockIdx.x;
    int h = threadIdx.x;
    __shared__ float xs[FDIM];
    if (h < FDIM) xs[h] = x[tok*FDIM + h];
    __syncthreads();
    float acc = bias[h];
    const float* wr = W + h*FDIM;
    #pragma unroll
    for (int f = 0; f < FDIM; f++) acc = fmaf(xs[f], wr[f], acc);
    g_h[tok*HDIM + h] = acc;
}

// ---------------- last-step projection ----------------
__global__ void k_lastproj(const float* __restrict__ x, const float* __restrict__ W,
                           const float* __restrict__ bias){
    int b = blockIdx.x;
    int h = threadIdx.x;
    __shared__ float xs[FDIM];
    if (h < FDIM) xs[h] = x[(b*LSEQ + (LSEQ-1))*FDIM + h];
    __syncthreads();
    float acc = bias[h];
    const float* wr = W + h*FDIM;
    #pragma unroll
    for (int f = 0; f < FDIM; f++) acc = fmaf(xs[f], wr[f], acc);
    g_last[b*HDIM + h] = acc;
}

// ---------------- layernorm over H=128: g_h -> g_hn (warp per token) ----------------
__global__ void k_ln(const float* __restrict__ gamma, const float* __restrict__ beta){
    int warp = (blockIdx.x*blockDim.x + threadIdx.x) >> 5;
    int lane = threadIdx.x & 31;
    const float* row = g_h + warp*HDIM;
    float v[4];
    float s = 0.f;
    #pragma unroll
    for (int i = 0; i < 4; i++){ v[i] = row[lane + 32*i]; s += v[i]; }
    #pragma unroll
    for (int o = 16; o > 0; o >>= 1) s += __shfl_xor_sync(0xffffffffu, s, o);
    float mu = s * (1.f/HDIM);
    float q = 0.f;
    #pragma unroll
    for (int i = 0; i < 4; i++){ float d = v[i]-mu; q = fmaf(d, d, q); }
    #pragma unroll
    for (int o = 16; o > 0; o >>= 1) q += __shfl_xor_sync(0xffffffffu, q, o);
    float rstd = rsqrtf(q * (1.f/HDIM) + 1e-5f);
    #pragma unroll
    for (int i = 0; i < 4; i++){
        int h = lane + 32*i;
        g_hn[warp*HDIM + h] = (v[i]-mu)*rstd*gamma[h] + beta[h];
    }
}

// ---------------- generic SGEMM-NT: C[m,n] = sum_k A[m,k]*B[n,k], fused epilogue ----------------
// EPI 0: A=g_hn, N=512,K=128 -> u (n<256) / silu(z) (n>=256)
// EPI 1: A=g_uc, N=40 ,K=256 -> g_xdb
// EPI 2: A=g_y , N=128,K=256 -> g_h += C (residual)
template<int EPI>
__global__ void sgemm_nt(const float* __restrict__ Bw, int N, int K){
    __shared__ __align__(16) float As[16][68];
    __shared__ __align__(16) float Bs[16][68];
    const float* A = (EPI==0) ? g_hn : (EPI==1) ? g_uc : g_y;
    int bm = blockIdx.y*64, bn = blockIdx.x*64;
    int tid = threadIdx.x;
    int tx = tid & 15, ty = tid >> 4;
    int lr = tid >> 2;            // 0..63
    int lc = (tid & 3) << 2;      // 0,4,8,12
    float acc[4][4];
    #pragma unroll
    for (int i = 0; i < 4; i++)
        #pragma unroll
        for (int j = 0; j < 4; j++) acc[i][j] = 0.f;
    const float* Ap = A + (bm+lr)*K + lc;
    bool bok = (bn + lr) < N;
    const float* Bp = Bw + (bok ? (bn+lr)*K + lc : 0);
    for (int k0 = 0; k0 < K; k0 += 16){
        float4 av = *(const float4*)(Ap + k0);
        float4 bv = bok ? *(const float4*)(Bp + k0) : make_float4(0.f,0.f,0.f,0.f);
        __syncthreads();
        As[lc+0][lr]=av.x; As[lc+1][lr]=av.y; As[lc+2][lr]=av.z; As[lc+3][lr]=av.w;
        Bs[lc+0][lr]=bv.x; Bs[lc+1][lr]=bv.y; Bs[lc+2][lr]=bv.z; Bs[lc+3][lr]=bv.w;
        __syncthreads();
        #pragma unroll
        for (int kk = 0; kk < 16; kk++){
            float4 ra = *(const float4*)&As[kk][ty<<2];
            float4 rb = *(const float4*)&Bs[kk][tx<<2];
            acc[0][0]=fmaf(ra.x,rb.x,acc[0][0]); acc[0][1]=fmaf(ra.x,rb.y,acc[0][1]);
            acc[0][2]=fmaf(ra.x,rb.z,acc[0][2]); acc[0][3]=fmaf(ra.x,rb.w,acc[0][3]);
            acc[1][0]=fmaf(ra.y,rb.x,acc[1][0]); acc[1][1]=fmaf(ra.y,rb.y,acc[1][1]);
            acc[1][2]=fmaf(ra.y,rb.z,acc[1][2]); acc[1][3]=fmaf(ra.y,rb.w,acc[1][3]);
            acc[2][0]=fmaf(ra.z,rb.x,acc[2][0]); acc[2][1]=fmaf(ra.z,rb.y,acc[2][1]);
            acc[2][2]=fmaf(ra.z,rb.z,acc[2][2]); acc[2][3]=fmaf(ra.z,rb.w,acc[2][3]);
            acc[3][0]=fmaf(ra.w,rb.x,acc[3][0]); acc[3][1]=fmaf(ra.w,rb.y,acc[3][1]);
            acc[3][2]=fmaf(ra.w,rb.z,acc[3][2]); acc[3][3]=fmaf(ra.w,rb.w,acc[3][3]);
        }
    }
    #pragma unroll
    for (int i = 0; i < 4; i++){
        int m = bm + (ty<<2) + i;
        #pragma unroll
        for (int j = 0; j < 4; j++){
            int n = bn + (tx<<2) + j;
            float v = acc[i][j];
            if (EPI == 0){
                if (n < DINNER) g_u[m*DINNER + n] = v;
                else            g_z[m*DINNER + (n-DINNER)] = siluf(v);
            } else if (EPI == 1){
                if (n < N) g_xdb[m*XDBW + n] = v;
            } else {
                g_h[m*HDIM + n] += v;
            }
        }
    }
}

// ---------------- depthwise causal conv (DC=4) + bias + silu ----------------
__global__ void k_conv(const float* __restrict__ cW, const float* __restrict__ cb){
    int idx = blockIdx.x*256 + threadIdx.x;
    int d = idx & (DINNER-1);
    int t = (idx >> 8) & (LSEQ-1);
    int b = idx >> 17;
    const float4 w = ((const float4*)cW)[d];
    int base = b*LSEQ*DINNER + d;
    float acc = cb[d];
    if (t >= 3) acc = fmaf(w.x, g_u[base + (t-3)*DINNER], acc);
    if (t >= 2) acc = fmaf(w.y, g_u[base + (t-2)*DINNER], acc);
    if (t >= 1) acc = fmaf(w.z, g_u[base + (t-1)*DINNER], acc);
    acc = fmaf(w.w, g_u[base + t*DINNER], acc);
    g_uc[idx] = siluf(acc);
}

// ---------------- dt = softplus(xdb[:, :8] @ dt_W^T + dt_b) ----------------
__global__ void k_dt(const float* __restrict__ dtW, const float* __restrict__ dtb){
    int tok = blockIdx.x;
    int d = threadIdx.x;
    __shared__ float xr[DTRANK];
    if (d < DTRANK) xr[d] = g_xdb[tok*XDBW + d];
    __syncthreads();
    float acc = dtb[d];
    const float* wr = dtW + d*DTRANK;
    #pragma unroll
    for (int r = 0; r < DTRANK; r++) acc = fmaf(xr[r], wr[r], acc);
    g_dt[tok*DINNER + d] = (acc > 20.f) ? acc : log1pf(__expf(acc));
}

// ---------------- selective scan + D skip + silu(z) gate ----------------
__global__ void k_scan(const float* __restrict__ A_log, const float* __restrict__ Dp){
    int b = blockIdx.x >> 1;
    int d = ((blockIdx.x & 1) << 7) + threadIdx.x;
    int tid = threadIdx.x;
    __shared__ float sBC[2][32];
    const float* xb = g_xdb + b*LSEQ*XDBW;
    if (tid < 32) sBC[0][tid] = xb[DTRANK + tid];
    float hs[DSTATE], An[DSTATE];
    #pragma unroll
    for (int n = 0; n < DSTATE; n++){
        hs[n] = 0.f;
        An[n] = -__expf(A_log[d*DSTATE + n]) * 1.4426950408889634f;  // A * log2(e)
    }
    float Dd = Dp[d];
    int base = b*LSEQ*DINNER + d;
    __syncthreads();
    for (int t = 0; t < LSEQ; t++){
        float uv  = g_uc[base + t*DINNER];
        float dtv = g_dt[base + t*DINNER];
        float zv  = g_z [base + t*DINNER];
        if (tid < 32 && t+1 < LSEQ) sBC[(t+1)&1][tid] = xb[(t+1)*XDBW + DTRANK + tid];
        const float* Bm = sBC[t&1];
        const float* Cm = Bm + DSTATE;
        float w = dtv*uv;
        float y = 0.f;
        #pragma unroll
        for (int n = 0; n < DSTATE; n++){
            float dA = exp2f(dtv*An[n]);
            hs[n] = fmaf(dA, hs[n], w*Bm[n]);
            y = fmaf(hs[n], Cm[n], y);
        }
        g_y[base + t*DINNER] = (y + uv*Dd) * zv;
        __syncthreads();
    }
}

// ---------------- query path: qk[b,h] = sum_k (last@q_W^T+q_b)[k]*k_W[k,h]; qbias = q.k_b ----------------
__global__ void k_query(const float* __restrict__ qW, const float* __restrict__ qb,
                        const float* __restrict__ kW, const float* __restrict__ kb){
    int b = blockIdx.x;
    int tid = threadIdx.x;   // 128
    __shared__ float lv[HDIM];
    __shared__ float qv[HDIM];
    __shared__ float red[HDIM];
    lv[tid] = g_last[b*HDIM + tid];
    __syncthreads();
    float acc = qb[tid];
    const float* wr = qW + tid*HDIM;
    #pragma unroll 4
    for (int h = 0; h < HDIM; h++) acc = fmaf(lv[h], wr[h], acc);
    qv[tid] = acc;
    __syncthreads();
    float a2 = 0.f;
    #pragma unroll 4
    for (int k = 0; k < HDIM; k++) a2 = fmaf(qv[k], kW[k*HDIM + tid], a2);
    g_qk[b*HDIM + tid] = a2;
    red[tid] = qv[tid]*kb[tid];
    __syncthreads();
    for (int s = 64; s > 0; s >>= 1){ if (tid < s) red[tid] += red[tid+s]; __syncthreads(); }
    if (tid == 0) g_qbias[b] = red[0];
}

// ---------------- masked softmax attention pooling ----------------
__global__ void k_attnpool(const float* __restrict__ x){
    int b = blockIdx.x;
    int tid = threadIdx.x;   // 256
    __shared__ float sq[HDIM];
    __shared__ float sw[LSEQ];
    __shared__ float red[256];
    if (tid < HDIM) sq[tid] = g_qk[b*HDIM + tid];
    __syncthreads();
    float qbv = g_qbias[b];
    const float* hf = g_hn + b*LSEQ*HDIM;
    for (int l = tid; l < LSEQ; l += 256){
        const float4* row = (const float4*)(hf + l*HDIM);
        float acc = 0.f;
        #pragma unroll
        for (int i = 0; i < HDIM/4; i++){
            float4 v = row[i];
            acc += v.x*sq[4*i] + v.y*sq[4*i+1] + v.z*sq[4*i+2] + v.w*sq[4*i+3];
        }
        float s = (acc + qbv) * ATTN_SCALE;
        float m = x[(b*LSEQ + l)*FDIM + (FDIM-1)];
        sw[l] = (m > 0.5f) ? s : -1e9f;
    }
    __syncthreads();
    float mx = -1e30f;
    for (int l = tid; l < LSEQ; l += 256) mx = fmaxf(mx, sw[l]);
    red[tid] = mx; __syncthreads();
    for (int s = 128; s > 0; s >>= 1){ if (tid < s) red[tid] = fmaxf(red[tid], red[tid+s]); __syncthreads(); }
    mx = red[0]; __syncthreads();
    float sum = 0.f;
    for (int l = tid; l < LSEQ; l += 256){ float e = __expf(sw[l]-mx); sw[l] = e; sum += e; }
    red[tid] = sum; __syncthreads();
    for (int s = 128; s > 0; s >>= 1){ if (tid < s) red[tid] += red[tid+s]; __syncthreads(); }
    float inv = 1.f/red[0];
    __syncthreads();
    for (int l = tid; l < LSEQ; l += 256) sw[l] *= inv;
    __syncthreads();
    if (tid < HDIM){
        float acc = 0.f;
        #pragma unroll 4
        for (int l = 0; l < LSEQ; l++) acc = fmaf(sw[l], hf[l*HDIM + tid], acc);
        g_sr[b*HDIM + tid] = acc + g_last[b*HDIM + tid];
    }
}

// ---------------- per-(b,e) head: gelu MLP -> logits ----------------
__global__ void k_heads(const float* __restrict__ h1W, const float* __restrict__ h1b,
                        const float* __restrict__ h2W, const float* __restrict__ h2b,
                        float* __restrict__ out){
    int b = blockIdx.x / NE, e = blockIdx.x % NE;
    int tid = threadIdx.x;   // 192
    __shared__ float sr[HDIM];
    __shared__ float hid[NFC];
    if (tid < HDIM) sr[tid] = g_sr[b*HDIM + tid];
    __syncthreads();
    if (tid < NFC){
        const float* wr = h1W + (e*NFC + tid)*HDIM;
        float acc = h1b[e*NFC + tid];
        #pragma unroll 4
        for (int h = 0; h < HDIM; h++) acc = fmaf(sr[h], wr[h], acc);
        hid[tid] = 0.5f*acc*(1.f + erff(acc*0.7071067811865475f));
    }
    __syncthreads();
    if (tid < NT){
        const float* wr = h2W + (e*NT + tid)*NFC;
        float acc = h2b[e*NT + tid];
        #pragma unroll 4
        for (int f = 0; f < NFC; f++) acc = fmaf(hid[f], wr[f], acc);
        out[(b*NE + e)*NT + tid] = acc;
    }
}

// ---------------- launch ----------------
extern "C" void kernel_launch(void* const* d_in, const int* in_sizes, int n_in,
                              void* d_out, int out_size){
    (void)in_sizes; (void)n_in; (void)out_size;
    const float* x    = (const float*)d_in[0];
    const float* ipW  = (const float*)d_in[1];
    const float* ipb  = (const float*)d_in[2];
    const float* iprW = (const float*)d_in[3];
    const float* iprb = (const float*)d_in[4];
    const float* lng  = (const float*)d_in[5];
    const float* lnb  = (const float*)d_in[6];
    const float* inW  = (const float*)d_in[7];
    const float* convW= (const float*)d_in[8];
    const float* convb= (const float*)d_in[9];
    const float* xpW  = (const float*)d_in[10];
    const float* dtW  = (const float*)d_in[11];
    const float* dtb  = (const float*)d_in[12];
    const float* Alog = (const float*)d_in[13];
    const float* Dp   = (const float*)d_in[14];
    const float* outW = (const float*)d_in[15];
    const float* ong  = (const float*)d_in[16];
    const float* onb  = (const float*)d_in[17];
    const float* qW   = (const float*)d_in[18];
    const float* qb   = (const float*)d_in[19];
    const float* kW   = (const float*)d_in[20];
    const float* kb   = (const float*)d_in[21];
    const float* h1W  = (const float*)d_in[22];
    const float* h1b  = (const float*)d_in[23];
    const float* h2W  = (const float*)d_in[24];
    const float* h2b  = (const float*)d_in[25];
    float* out = (float*)d_out;

    k_inproj<<<BL, HDIM>>>(x, ipW, ipb);
    k_lastproj<<<BATCH, HDIM>>>(x, iprW, iprb);

    for (int l = 0; l < NLAYER; l++){
        k_ln<<<BL/8, 256>>>(lng + l*HDIM, lnb + l*HDIM);
        sgemm_nt<0><<<dim3(8,  BL/64), 256>>>(inW + l*2*DINNER*HDIM, 2*DINNER, HDIM);
        k_conv<<<BL*DINNER/256, 256>>>(convW + l*DINNER*DCONV, convb + l*DINNER);
        sgemm_nt<1><<<dim3(1,  BL/64), 256>>>(xpW + l*XDBW*DINNER, XDBW, DINNER);
        k_dt<<<BL, DINNER>>>(dtW + l*DINNER*DTRANK, dtb + l*DINNER);
        k_scan<<<BATCH*2, 128>>>(Alog + l*DINNER*DSTATE, Dp + l*DINNER);
        sgemm_nt<2><<<dim3(2,  BL/64), 256>>>(outW + l*HDIM*DINNER, HDIM, DINNER);
    }

    k_ln<<<BL/8, 256>>>(ong, onb);                 // final LN -> g_hn
    k_query<<<BATCH, HDIM>>>(qW, qb, kW, kb);
    k_attnpool<<<BATCH, 256>>>(x);
    k_heads<<<BATCH*NE, 192>>>(h1W, h1b, h2W, h2b, out);
}